// round 11
// baseline (speedup 1.0000x reference)
#include <cuda_runtime.h>
#include <cuda_bf16.h>
#include <mma.h>
#include <math.h>
#include <stdint.h>

using namespace nvcuda;

#define Bdim 128
#define Tdim 512
#define Idim 300
#define Hdim 256
#define G4H  1024   // 4*H gate rows
#define NSTEP 512

#define KBLK 5      // K padded 300 -> 320 = 5 blocks of 64 bf16
#define GPITCH 72   // smem pitch (bf16 elems) for gemm_wmma tiles

typedef unsigned long long u64;

// ---------------------------------------------------------------------------
// Scratch (static __device__ globals; no allocation anywhere)
// ---------------------------------------------------------------------------
__device__ float g_xp[(size_t)Bdim * Tdim * G4H];   // 256 MB: x @ W_ih_f^T (no bias)
__device__ float g_xpb[Bdim * G4H];                 // backward projection at t=T-1
__device__ float g_h[2][Bdim][Hdim];                // double-buffered hidden state
__device__ unsigned int g_bar[16];                  // per-batch-group barrier counters

// packed bf16 hi/lo operand tiles, plain linear layout:
__device__ uint4 g_Ah[(size_t)512 * KBLK * 1024];
__device__ uint4 g_Al[(size_t)512 * KBLK * 1024];
__device__ uint4 g_Bh[8 * KBLK * 1024];
__device__ uint4 g_Bl[8 * KBLK * 1024];

// ---------------------------------------------------------------------------
// packed f32x2 helpers (PTX fma.rn.f32x2 — base sm_100-family, no 'a' suffix)
// ---------------------------------------------------------------------------
__device__ __forceinline__ u64 pack2(float x, float y) {
    u64 r; asm("mov.b64 %0, {%1, %2};" : "=l"(r) : "f"(x), "f"(y)); return r;
}
__device__ __forceinline__ u64 fma2(u64 a, u64 b, u64 c) {
    u64 d;
    asm("fma.rn.f32x2 %0, %1, %2, %3;" : "=l"(d) : "l"(a), "l"(b), "l"(c));
    return d;
}

// ---------------------------------------------------------------------------
__global__ void init_k()
{
    int i = blockIdx.x * blockDim.x + threadIdx.x;
    if (i < Bdim * Hdim) ((float*)g_h)[i] = 0.f;
    if (i < 16) g_bar[i] = 0u;
}

// ---------------------------------------------------------------------------
// conv_pack: fp32 rows [rows x Idim] -> bf16 hi/lo packed tiles (linear).
// ---------------------------------------------------------------------------
__global__ void conv_pack(const float* __restrict__ src, int rows,
                          uint4* __restrict__ Hc, uint4* __restrict__ Lc)
{
    int id = blockIdx.x * blockDim.x + threadIdx.x;
    int total = rows * 40;
    if (id >= total) return;
    int m  = id / 40;
    int g  = id % 40;
    int k0 = g * 8;

    union U8 { uint4 u; __nv_bfloat16 b[8]; } hu, lu;
#pragma unroll
    for (int j = 0; j < 8; j++) {
        int k = k0 + j;
        float v = (k < Idim) ? src[(size_t)m * Idim + k] : 0.f;
        __nv_bfloat16 h = __float2bfloat16(v);
        hu.b[j] = h;
        lu.b[j] = __float2bfloat16(v - __bfloat162float(h));
    }

    int tile = m >> 7;
    int r    = m & 127;
    int blk  = k0 >> 6;
    int c8   = (k0 & 63) >> 3;
    size_t idx = ((size_t)tile * KBLK + blk) * 1024 + (size_t)r * 8 + c8;
    Hc[idx] = hu.u;
    Lc[idx] = lu.u;
}

// ---------------------------------------------------------------------------
// gemm_wmma: xp = x @ W_ih_f^T, split-bf16 HMMA.
// R11: 2 CTAs/SM (reg cap) + dedup'd fragment loads (48 LDSM/warp/blk).
// ---------------------------------------------------------------------------
#define GEMM_SMEM (4 * 128 * GPITCH * 2)

__global__ void __launch_bounds__(256, 2) gemm_wmma(
    const uint4* __restrict__ Ah, const uint4* __restrict__ Al,
    const uint4* __restrict__ Bh, const uint4* __restrict__ Bl,
    float* __restrict__ C)
{
    extern __shared__ __nv_bfloat16 sm[];
    __nv_bfloat16* sAh = sm;
    __nv_bfloat16* sAl = sm + 128 * GPITCH;
    __nv_bfloat16* sBh = sm + 2 * 128 * GPITCH;
    __nv_bfloat16* sBl = sm + 3 * 128 * GPITCH;

    int tid = threadIdx.x;
    int wid = tid >> 5;
    int wm  = wid >> 2;
    int wn  = wid & 3;
    int nt  = blockIdx.x;
    int mt  = blockIdx.y;

    wmma::fragment<wmma::accumulator, 16, 16, 16, float> acc[4][2];
#pragma unroll
    for (int i = 0; i < 4; i++)
#pragma unroll
        for (int j = 0; j < 2; j++) wmma::fill_fragment(acc[i][j], 0.f);

    for (int blk = 0; blk < KBLK; blk++) {
        const uint4* gA_h = Ah + ((size_t)mt * KBLK + blk) * 1024;
        const uint4* gA_l = Al + ((size_t)mt * KBLK + blk) * 1024;
        const uint4* gB_h = Bh + ((size_t)nt * KBLK + blk) * 1024;
        const uint4* gB_l = Bl + ((size_t)nt * KBLK + blk) * 1024;
        uint4* dAh = (uint4*)sAh;
        uint4* dAl = (uint4*)sAl;
        uint4* dBh = (uint4*)sBh;
        uint4* dBl = (uint4*)sBl;
#pragma unroll
        for (int it = 0; it < 4; it++) {
            int i = it * 256 + tid;
            int r = i >> 3, c = i & 7;
            int d = r * 9 + c;
            dAh[d] = gA_h[i];
            dAl[d] = gA_l[i];
            dBh[d] = gB_h[i];
            dBl[d] = gB_l[i];
        }
        __syncthreads();

#pragma unroll
        for (int ks = 0; ks < 4; ks++) {
            wmma::fragment<wmma::matrix_a, 16, 16, 16, __nv_bfloat16,
                           wmma::row_major> afh[4], afl[4];
            wmma::fragment<wmma::matrix_b, 16, 16, 16, __nv_bfloat16,
                           wmma::col_major> bh[2], bl[2];
#pragma unroll
            for (int i = 0; i < 4; i++)
                wmma::load_matrix_sync(
                    afh[i], sAh + (wm * 64 + i * 16) * GPITCH + ks * 16, GPITCH);
#pragma unroll
            for (int j = 0; j < 2; j++) {
                wmma::load_matrix_sync(
                    bh[j], sBh + (wn * 32 + j * 16) * GPITCH + ks * 16, GPITCH);
                wmma::load_matrix_sync(
                    bl[j], sBl + (wn * 32 + j * 16) * GPITCH + ks * 16, GPITCH);
            }
#pragma unroll
            for (int i = 0; i < 4; i++)
#pragma unroll
                for (int j = 0; j < 2; j++) {
                    wmma::mma_sync(acc[i][j], afh[i], bh[j], acc[i][j]);
                    wmma::mma_sync(acc[i][j], afh[i], bl[j], acc[i][j]);
                }
#pragma unroll
            for (int i = 0; i < 4; i++)
                wmma::load_matrix_sync(
                    afl[i], sAl + (wm * 64 + i * 16) * GPITCH + ks * 16, GPITCH);
#pragma unroll
            for (int i = 0; i < 4; i++)
#pragma unroll
                for (int j = 0; j < 2; j++)
                    wmma::mma_sync(acc[i][j], afl[i], bh[j], acc[i][j]);
        }
        __syncthreads();
    }

    size_t row0 = (size_t)mt * 128 + wm * 64;
    int    col0 = nt * 128 + wn * 32;
#pragma unroll
    for (int i = 0; i < 4; i++)
#pragma unroll
        for (int j = 0; j < 2; j++)
            wmma::store_matrix_sync(
                C + (row0 + i * 16) * G4H + col0 + j * 16,
                acc[i][j], G4H, wmma::mem_row_major);
}

// ---------------------------------------------------------------------------
// fp32 SGEMM (tiny backward projection at t = T-1; includes bias)
// ---------------------------------------------------------------------------
__global__ void __launch_bounds__(256) sgemm_bias(
    const float* __restrict__ A, long lda,
    const float* __restrict__ W,
    const float* __restrict__ bias,
    float* __restrict__ C)
{
    __shared__ float As[8][128];
    __shared__ float Bs[8][128];
    int tid  = threadIdx.x;
    long row0 = (long)blockIdx.y * 128;
    int  col0 = blockIdx.x * 128;
    int  lm = tid >> 1;
    int  lk = (tid & 1) * 4;
    int  tx = tid & 15, ty = tid >> 4;

    float bsv[8];
    *(float4*)(bsv)     = *(const float4*)&bias[col0 + tx * 8];
    *(float4*)(bsv + 4) = *(const float4*)&bias[col0 + tx * 8 + 4];

    float acc[8][8];
#pragma unroll
    for (int i = 0; i < 8; i++)
#pragma unroll
        for (int j = 0; j < 8; j++) acc[i][j] = 0.f;

    for (int k0 = 0; k0 < Idim; k0 += 8) {
        float4 av = make_float4(0.f, 0.f, 0.f, 0.f);
        float4 bv = make_float4(0.f, 0.f, 0.f, 0.f);
        if (k0 + lk < Idim) {
            av = *(const float4*)(A + (row0 + lm) * lda + k0 + lk);
            bv = *(const float4*)(W + (long)(col0 + lm) * Idim + k0 + lk);
        }
        __syncthreads();
        As[lk + 0][lm] = av.x; As[lk + 1][lm] = av.y;
        As[lk + 2][lm] = av.z; As[lk + 3][lm] = av.w;
        Bs[lk + 0][lm] = bv.x; Bs[lk + 1][lm] = bv.y;
        Bs[lk + 2][lm] = bv.z; Bs[lk + 3][lm] = bv.w;
        __syncthreads();
#pragma unroll
        for (int k = 0; k < 8; k++) {
            float a[8], b[8];
            *(float4*)(a)     = *(const float4*)&As[k][ty * 8];
            *(float4*)(a + 4) = *(const float4*)&As[k][ty * 8 + 4];
            *(float4*)(b)     = *(const float4*)&Bs[k][tx * 8];
            *(float4*)(b + 4) = *(const float4*)&Bs[k][tx * 8 + 4];
#pragma unroll
            for (int i = 0; i < 8; i++)
#pragma unroll
                for (int j = 0; j < 8; j++)
                    acc[i][j] = fmaf(a[i], b[j], acc[i][j]);
        }
    }

#pragma unroll
    for (int i = 0; i < 8; i++) {
        long r = row0 + ty * 8 + i;
        float4 o0 = make_float4(acc[i][0] + bsv[0], acc[i][1] + bsv[1],
                                acc[i][2] + bsv[2], acc[i][3] + bsv[3]);
        float4 o1 = make_float4(acc[i][4] + bsv[4], acc[i][5] + bsv[5],
                                acc[i][6] + bsv[6], acc[i][7] + bsv[7]);
        *(float4*)&C[r * G4H + col0 + tx * 8]     = o0;
        *(float4*)&C[r * G4H + col0 + tx * 8 + 4] = o1;
    }
}

// ---------------------------------------------------------------------------
// Persistent forward LSTM recurrence — R4 structure (proven) with the GEMM
// inner loop on packed fma.rn.f32x2 (2x fp32 FMA throughput).
// Thread GEMM rows are pairs {2*r8+32i, 2*r8+32i+1}; W reads are LDS.64,
// 16 lanes x 8B = 128B contiguous per half-warp (conflict-free, broadcast
// across the two half-warps). Pitch 130 keeps 8B alignment.
// ---------------------------------------------------------------------------
#define WPITCH 130
#define SMEM_FLOATS (Hdim * WPITCH + 8 * Hdim + 8 * G4H)
#define SMEM_BYTES  (SMEM_FLOATS * 4)

__device__ __forceinline__ float sigf(float x) { return 1.f / (1.f + __expf(-x)); }

__global__ void __launch_bounds__(256, 1) lstm_fwd(const float* __restrict__ Whh,
                                                   const float* __restrict__ bias)
{
    extern __shared__ float sm_f[];
    float* Wsh  = sm_f;                       // [256][130] transposed W tile
    float* hsh  = sm_f + Hdim * WPITCH;       // [8][256]   h for this batch tile
    float* part = hsh + 8 * Hdim;             // [8][1024]  k-split partials

    int tid = threadIdx.x;
    int gb  = blockIdx.x >> 3;
    int gj  = blockIdx.x & 7;
    int b0  = gb * 8;
    int j0  = gj * 32;

    for (int idx = tid; idx < 128 * Hdim; idx += 256) {
        int lr = idx >> 8;
        int k  = idx & 255;
        int grow = ((lr >> 5) << 8) + j0 + (lr & 31);
        Wsh[k * WPITCH + lr] = Whh[grow * Hdim + k];
    }

    int ks    = tid >> 5;
    int lane  = tid & 31;
    int bg    = lane >> 4;
    int r8    = lane & 15;
    int kbase = ks * 32;
    int bred  = tid >> 5;
    int jj    = tid & 31;

    float bgate[4];
#pragma unroll
    for (int g = 0; g < 4; g++) bgate[g] = bias[g * 256 + j0 + jj];

    float c = 0.f;
    volatile unsigned int* barp = &g_bar[gb];
    __syncthreads();

    for (int t = 0; t < NSTEP; t++) {
        float xg[4];
        {
            size_t base = ((size_t)(b0 + bred) * Tdim + t) * G4H + j0 + jj;
#pragma unroll
            for (int g = 0; g < 4; g++) xg[g] = g_xp[base + (size_t)g * 256];
        }

        int p = t & 1;
        {
            const float4* src = (const float4*)&g_h[p][b0][0];
            float4* dst = (float4*)hsh;
            for (int i = tid; i < 512; i += 256) dst[i] = src[i];
        }
        __syncthreads();

        // GEMM slice on f32x2: acc2[bi][i] = row pair {2*r8+32i, +1}
        u64 acc2[4][4];
#pragma unroll
        for (int bi = 0; bi < 4; bi++)
#pragma unroll
            for (int i = 0; i < 4; i++) acc2[bi][i] = 0ull;

#pragma unroll
        for (int k = 0; k < 32; k += 4) {
            float4 hv[4];
#pragma unroll
            for (int bi = 0; bi < 4; bi++)
                hv[bi] = *(const float4*)&hsh[(bg * 4 + bi) * Hdim + kbase + k];
#pragma unroll
            for (int kk = 0; kk < 4; kk++) {
                const float* wr = &Wsh[(kbase + k + kk) * WPITCH + 2 * r8];
                u64 w2[4];
#pragma unroll
                for (int i = 0; i < 4; i++)
                    w2[i] = *(const u64*)(wr + 32 * i);
#pragma unroll
                for (int bi = 0; bi < 4; bi++) {
                    float hval = ((const float*)&hv[bi])[kk];
                    u64 h2 = pack2(hval, hval);
#pragma unroll
                    for (int i = 0; i < 4; i++)
                        acc2[bi][i] = fma2(h2, w2[i], acc2[bi][i]);
                }
            }
        }

        // write k-slice partials (pairs, STS.64 aligned)
#pragma unroll
        for (int bi = 0; bi < 4; bi++)
#pragma unroll
            for (int i = 0; i < 4; i++)
                *(u64*)&part[ks * G4H + (bg * 4 + bi) * 128 + 2 * r8 + 32 * i]
                    = acc2[bi][i];
        __syncthreads();

        // reduce 8 slices + gates + state update; thread owns (bred, jj)
        float gsum[4];
#pragma unroll
        for (int g = 0; g < 4; g++) {
            float s = xg[g] + bgate[g];
#pragma unroll
            for (int kss = 0; kss < 8; kss++)
                s += part[kss * G4H + bred * 128 + g * 32 + jj];
            gsum[g] = s;
        }
        float ig = sigf(gsum[0]);
        float fg = sigf(gsum[1]);
        float gg = tanhf(gsum[2]);
        float og = sigf(gsum[3]);
        c = fg * c + ig * gg;
        float h = og * tanhf(c);
        g_h[p ^ 1][b0 + bred][j0 + jj] = h;
        __syncthreads();

        if (t < NSTEP - 1) {
            if (tid == 0) {
                __threadfence();
                atomicAdd(&g_bar[gb], 1u);
                unsigned target = 8u * (unsigned)(t + 1);
                while (*barp < target) { }
                __threadfence();
            }
            __syncthreads();
        }
    }
}

// ---------------------------------------------------------------------------
// Final: hb_last = ONE backward step from zero state on x[:,T-1]
// ---------------------------------------------------------------------------
__global__ void final_k(const float* __restrict__ Wlin,
                        const float* __restrict__ blin,
                        float* __restrict__ out)
{
    int b = threadIdx.x;
    float a0 = blin[0], a1 = blin[1];
    const float* hf = &g_h[0][b][0];
#pragma unroll 4
    for (int j = 0; j < Hdim; j++) {
        float h = hf[j];
        a0 = fmaf(h, Wlin[j], a0);
        a1 = fmaf(h, Wlin[512 + j], a1);
    }
    const float* xb = &g_xpb[b * G4H];
#pragma unroll 4
    for (int j = 0; j < Hdim; j++) {
        float ig = 1.f / (1.f + __expf(-xb[j]));
        float gg = tanhf(xb[512 + j]);
        float og = 1.f / (1.f + __expf(-xb[768 + j]));
        float cc = ig * gg;
        float h  = og * tanhf(cc);
        a0 = fmaf(h, Wlin[256 + j], a0);
        a1 = fmaf(h, Wlin[768 + j], a1);
    }
    out[b * 2]     = a0;
    out[b * 2 + 1] = a1;
}

// ---------------------------------------------------------------------------
// launch
// ---------------------------------------------------------------------------
extern "C" void kernel_launch(void* const* d_in, const int* in_sizes, int n_in,
                              void* d_out, int out_size)
{
    const float* x    = (const float*)d_in[0];
    const float* Wihf = (const float*)d_in[1];
    const float* Whhf = (const float*)d_in[2];
    const float* bf   = (const float*)d_in[3];
    const float* Wihb = (const float*)d_in[4];
    // d_in[5] = W_hh_b: unused (backward output only needs its first step)
    const float* bb   = (const float*)d_in[6];
    const float* Wlin = (const float*)d_in[7];
    const float* blin = (const float*)d_in[8];
    float* out = (float*)d_out;

    void *xp_ptr = nullptr, *xpb_ptr = nullptr;
    void *ah = nullptr, *al = nullptr, *bh = nullptr, *bl = nullptr;
    cudaGetSymbolAddress(&xp_ptr,  g_xp);
    cudaGetSymbolAddress(&xpb_ptr, g_xpb);
    cudaGetSymbolAddress(&ah, g_Ah);
    cudaGetSymbolAddress(&al, g_Al);
    cudaGetSymbolAddress(&bh, g_Bh);
    cudaGetSymbolAddress(&bl, g_Bl);

    cudaFuncSetAttribute(gemm_wmma, cudaFuncAttributeMaxDynamicSharedMemorySize,
                         GEMM_SMEM);
    cudaFuncSetAttribute(lstm_fwd, cudaFuncAttributeMaxDynamicSharedMemorySize,
                         SMEM_BYTES);

    init_k<<<128, 256>>>();

    // split-bf16 operand packing (plain linear tiles)
    conv_pack<<<(65536 * 40 + 255) / 256, 256>>>(x, 65536, (uint4*)ah, (uint4*)al);
    conv_pack<<<(1024 * 40 + 255) / 256, 256>>>(Wihf, 1024, (uint4*)bh, (uint4*)bl);

    // xp_f = x @ W_ih_f^T on HMMA tensor path
    gemm_wmma<<<dim3(8, 512), 256, GEMM_SMEM>>>(
        (const uint4*)ah, (const uint4*)al, (const uint4*)bh, (const uint4*)bl,
        (float*)xp_ptr);

    // backward projection at t = T-1 only (tiny, fp32, bias included)
    sgemm_bias<<<dim3(8, 1), 256>>>(x + (long)(Tdim - 1) * Idim,
                                    (long)Tdim * Idim, Wihb, bb,
                                    (float*)xpb_ptr);

    // persistent fp32x2 FFMA recurrence (16 batch groups x 8 col groups)
    lstm_fwd<<<128, 256, SMEM_BYTES>>>(Whhf, bf);

    // epilogue
    final_k<<<1, 128>>>(Wlin, blin, out);
}